// round 4
// baseline (speedup 1.0000x reference)
#include <cuda_runtime.h>
#include <cuda_bf16.h>
#include <math.h>

// Problem constants
#define BB 8
#define TT 8192
#define DD 128
#define SS 128
#define CK 64
#define NC (TT / CK)          // 128 chunks per batch
#define NBLK (BB * NC)        // 1024 chunk-CTAs
#define WPITCH 132            // padded smem pitch for weight tiles (conflict-free LDS.128)

// Scratch (device globals; no runtime allocation allowed)
__device__ float g_hloc[BB * TT * SS];   // h with h0=0 (per chunk)
__device__ float g_p[BB * TT * SS];      // decay prefix p_t (per chunk)
__device__ float g_C[BB * TT * SS];      // C = x @ W_C^T
__device__ float g_carry[BB * NC * SS];  // h0 entering each chunk

// ---------------------------------------------------------------------------
// Shared helpers
// ---------------------------------------------------------------------------

// Load a 128x128 row-major weight matrix into smem with padded pitch.
__device__ __forceinline__ void load_w(float* wp, const float* __restrict__ Wg, int tid) {
    const float4* wg4 = (const float4*)Wg;
#pragma unroll
    for (int k = 0; k < 16; k++) {
        int f = tid + k * 256;          // float4 index, 4096 total
        int s = f >> 5;                 // row (32 float4 per row)
        int dv = f & 31;
        *(float4*)(wp + s * WPITCH + dv * 4) = wg4[f];
    }
}

// 64x128 output tile GEMM: out[t][s] = sum_d xs[t][d] * wp[s][d]
// Thread (tx,ty): rows 8*ty..+7, cols 4*tx..+3.
__device__ __forceinline__ void gemm_tile(const float* __restrict__ xs,
                                          const float* __restrict__ wp,
                                          int rowb, int col, float acc[8][4]) {
#pragma unroll
    for (int j = 0; j < 8; j++)
#pragma unroll
        for (int i = 0; i < 4; i++) acc[j][i] = 0.0f;

#pragma unroll 2
    for (int d0 = 0; d0 < 128; d0 += 4) {
        float4 xv[8];
#pragma unroll
        for (int j = 0; j < 8; j++)
            xv[j] = *(const float4*)(xs + (rowb + j) * 128 + d0);
        float4 wv[4];
#pragma unroll
        for (int i = 0; i < 4; i++)
            wv[i] = *(const float4*)(wp + (col + i) * WPITCH + d0);
#pragma unroll
        for (int j = 0; j < 8; j++) {
#pragma unroll
            for (int i = 0; i < 4; i++) {
                acc[j][i] = fmaf(xv[j].x, wv[i].x, acc[j][i]);
                acc[j][i] = fmaf(xv[j].y, wv[i].y, acc[j][i]);
                acc[j][i] = fmaf(xv[j].z, wv[i].z, acc[j][i]);
                acc[j][i] = fmaf(xv[j].w, wv[i].w, acc[j][i]);
            }
        }
    }
}

// ---------------------------------------------------------------------------
// K1: per-chunk fused GEMMs (dt, B, C) + pointwise + local chunk scan
// smem: xs[64*128] | wp[128*WPITCH] | la[64*128] | uu[64*128]
// ---------------------------------------------------------------------------
extern __shared__ float sm[];

__global__ void __launch_bounds__(256, 1)
k1_gemm_scan(const float* __restrict__ x, const float* __restrict__ log_A,
             const float* __restrict__ W_B, const float* __restrict__ W_C,
             const float* __restrict__ W_dt, const float* __restrict__ b_dt) {
    float* xs = sm;                       // 8192 floats
    float* wp = xs + CK * 128;            // 16896
    float* la = wp + 128 * WPITCH;        // 8192
    float* uu = la + CK * 128;            // 8192

    const int blk = blockIdx.x;
    const int b = blk / NC, c = blk % NC;
    const int row0 = b * TT + c * CK;     // global row index of chunk start
    const int tid = threadIdx.x;

    // Load x tile (64 rows x 128)
    {
        const float4* xg = (const float4*)(x + (size_t)row0 * DD);
        float4* xs4 = (float4*)xs;
#pragma unroll
        for (int k = 0; k < 8; k++) xs4[tid + k * 256] = xg[tid + k * 256];
    }

    const int tx = tid & 31, ty = tid >> 5;
    const int col = tx * 4, rowb = ty * 8;

    // Per-column constants
    float Ai[4], bi[4];
#pragma unroll
    for (int i = 0; i < 4; i++) {
        bi[i] = b_dt[col + i];
        Ai[i] = -fminf(expf(log_A[col + i]), 10.0f);
    }

    float acc[8][4];
    float dtreg[8][4];

    // ---- dt = min(softplus(x@W_dt^T + b_dt), 1); la = clip(dt*A, -0.5, 0) ----
    load_w(wp, W_dt, tid);
    __syncthreads();  // xs + wp ready
    gemm_tile(xs, wp, rowb, col, acc);
#pragma unroll
    for (int j = 0; j < 8; j++) {
        float4 lv;
        float* lvp = &lv.x;
#pragma unroll
        for (int i = 0; i < 4; i++) {
            float z = acc[j][i] + bi[i];
            float sp = fmaxf(z, 0.0f) + log1pf(__expf(-fabsf(z)));
            float dtv = fminf(sp, 1.0f);
            dtreg[j][i] = dtv;
            lvp[i] = fminf(fmaxf(dtv * Ai[i], -0.5f), 0.0f);
        }
        *(float4*)(la + (rowb + j) * 128 + col) = lv;
    }
    __syncthreads();  // wp reads done

    // ---- u = (x@W_B^T) * dt ----
    load_w(wp, W_B, tid);
    __syncthreads();
    gemm_tile(xs, wp, rowb, col, acc);
#pragma unroll
    for (int j = 0; j < 8; j++) {
        float4 uv;
        float* uvp = &uv.x;
#pragma unroll
        for (int i = 0; i < 4; i++) uvp[i] = acc[j][i] * dtreg[j][i];
        *(float4*)(uu + (rowb + j) * 128 + col) = uv;
    }
    __syncthreads();  // wp reads done + la/uu visible

    // ---- C = x@W_C^T -> global ----
    load_w(wp, W_C, tid);
    __syncthreads();
    gemm_tile(xs, wp, rowb, col, acc);
#pragma unroll
    for (int j = 0; j < 8; j++) {
        float4 cv = make_float4(acc[j][0], acc[j][1], acc[j][2], acc[j][3]);
        *(float4*)(g_C + (size_t)(row0 + rowb + j) * SS + col) = cv;
    }

    // ---- local chunk scan (h0 = 0): hloc_t = p_t * S_t ----
    if (tid < 128) {
        const int s = tid;
        float cum = 0.0f, Ssum = 0.0f;
#pragma unroll 4
        for (int t = 0; t < CK; t++) {
            cum += la[t * 128 + s];
            float logp = fmaxf(fminf(cum, 0.0f), -30.0f);
            float pv = __expf(logp);
            float pinv = __expf(-logp);
            Ssum = fmaf(uu[t * 128 + s], pinv, Ssum);
            size_t idx = (size_t)(row0 + t) * SS + s;
            g_hloc[idx] = pv * Ssum;
            g_p[idx] = pv;
        }
    }
}

// ---------------------------------------------------------------------------
// K2: cross-chunk carry scan: h0_{c+1} = hloc_last_c + p_last_c * h0_c
// grid = B blocks, 128 threads (one state each)
// ---------------------------------------------------------------------------
__global__ void k2_carry() {
    const int b = blockIdx.x;
    const int s = threadIdx.x;
    float h0 = 0.0f;
    for (int c0 = 0; c0 < NC; c0 += 16) {
        float hl[16], pp[16];
#pragma unroll
        for (int k = 0; k < 16; k++) {
            size_t idx = (size_t)(b * TT + (c0 + k) * CK + (CK - 1)) * SS + s;
            hl[k] = g_hloc[idx];
            pp[k] = g_p[idx];
        }
#pragma unroll
        for (int k = 0; k < 16; k++) {
            g_carry[(size_t)(b * NC + c0 + k) * SS + s] = h0;
            h0 = fmaf(pp[k], h0, hl[k]);
        }
    }
}

// ---------------------------------------------------------------------------
// K3: h = hloc + p*h0; y = sum_s(C*h); out = h@W_out^T + y*x[...,0]
// smem: hs[64*128] | wp[128*WPITCH] | ysh[64] | h0s[128] | x0s[64]
// ---------------------------------------------------------------------------
__global__ void __launch_bounds__(256, 1)
k3_output(const float* __restrict__ x, const float* __restrict__ W_out,
          float* __restrict__ out) {
    float* hs = sm;                       // 8192
    float* wp = hs + CK * 128;            // 16896
    float* ysh = wp + 128 * WPITCH;       // 64
    float* h0s = ysh + 64;                // 128
    float* x0s = h0s + 128;               // 64

    const int blk = blockIdx.x;
    const int b = blk / NC, c = blk % NC;
    const int row0 = b * TT + c * CK;
    const int tid = threadIdx.x;

    if (tid < 128) h0s[tid] = g_carry[(size_t)(b * NC + c) * SS + tid];
    if (tid >= 128 && tid < 192) x0s[tid - 128] = x[(size_t)(row0 + tid - 128) * DD];
    load_w(wp, W_out, tid);
    __syncthreads();

    // h tile: h = hloc + p * h0
    {
        const float4* hl4 = (const float4*)(g_hloc + (size_t)row0 * SS);
        const float4* pp4 = (const float4*)(g_p + (size_t)row0 * SS);
        float4* hs4 = (float4*)hs;
#pragma unroll
        for (int k = 0; k < 8; k++) {
            int f = tid + k * 256;
            int sv = f & 31;
            float4 hv = hl4[f];
            float4 pv = pp4[f];
            float4 h0v = *(const float4*)(h0s + sv * 4);
            hv.x = fmaf(pv.x, h0v.x, hv.x);
            hv.y = fmaf(pv.y, h0v.y, hv.y);
            hv.z = fmaf(pv.z, h0v.z, hv.z);
            hv.w = fmaf(pv.w, h0v.w, hv.w);
            hs4[f] = hv;
        }
    }
    __syncthreads();

    // y[t] = sum_s C[t][s] * h[t][s]  (4 threads per row)
    {
        const int r = tid >> 2, q = tid & 3;
        float ysum = 0.0f;
        const float4* Cr = (const float4*)(g_C + (size_t)(row0 + r) * SS);
#pragma unroll
        for (int k = 0; k < 8; k++) {
            float4 c4 = Cr[q * 8 + k];
            float4 h4 = *(const float4*)(hs + r * 128 + q * 32 + k * 4);
            ysum += c4.x * h4.x + c4.y * h4.y + c4.z * h4.z + c4.w * h4.w;
        }
        ysum += __shfl_xor_sync(0xffffffffu, ysum, 1);
        ysum += __shfl_xor_sync(0xffffffffu, ysum, 2);
        if (q == 0) ysh[r] = ysum;
    }
    __syncthreads();

    // out GEMM: out[t][d] = sum_s h[t][s]*W_out[d][s] + y[t]*x0[t]
    const int tx = tid & 31, ty = tid >> 5;
    const int col = tx * 4, rowb = ty * 8;
    float acc[8][4];
    gemm_tile(hs, wp, rowb, col, acc);
#pragma unroll
    for (int j = 0; j < 8; j++) {
        float yx = ysh[rowb + j] * x0s[rowb + j];
        float4 v = make_float4(acc[j][0] + yx, acc[j][1] + yx,
                               acc[j][2] + yx, acc[j][3] + yx);
        *(float4*)(out + (size_t)(row0 + rowb + j) * DD + col) = v;
    }
}

// ---------------------------------------------------------------------------
// Launch
// ---------------------------------------------------------------------------
extern "C" void kernel_launch(void* const* d_in, const int* in_sizes, int n_in,
                              void* d_out, int out_size) {
    const float* x = (const float*)d_in[0];
    const float* log_A = (const float*)d_in[1];
    const float* W_B = (const float*)d_in[2];
    const float* W_C = (const float*)d_in[3];
    const float* W_dt = (const float*)d_in[4];
    const float* b_dt = (const float*)d_in[5];
    const float* W_out = (const float*)d_in[6];
    float* out = (float*)d_out;

    const int smem1 = (CK * 128 + 128 * WPITCH + 2 * CK * 128) * 4;      // 165,888 B
    const int smem3 = (CK * 128 + 128 * WPITCH + 64 + 128 + 64) * 4;     // 101,376 B

    cudaFuncSetAttribute(k1_gemm_scan, cudaFuncAttributeMaxDynamicSharedMemorySize, smem1);
    cudaFuncSetAttribute(k3_output, cudaFuncAttributeMaxDynamicSharedMemorySize, smem3);

    k1_gemm_scan<<<NBLK, 256, smem1>>>(x, log_A, W_B, W_C, W_dt, b_dt);
    k2_carry<<<BB, 128>>>();
    k3_output<<<NBLK, 256, smem3>>>(x, W_out, out);
}